// round 15
// baseline (speedup 1.0000x reference)
#include <cuda_runtime.h>
#include <cuda_bf16.h>

// Wav2Frames: out[b, c, f] = x[b, f*WINSTEP + c]
// x: (32, 1, 480000) fp32 -> out: (32, 400, 2998) fp32
//
// R15: R10's confirmed mechanisms at 4 CTAs/SM granularity.
//   Hypothesis: 4x512-thread CTAs interleave fill/drain phases per SM more
//   finely than 2x1024 (less bursty DRAM R/W alternation at barriers).
//   Kept identical: per-row sector shift s(c)=(2c)&7 (RMW win), smem skew
//   j+(j>>5), float4 LDG fill, float2 frame-pair stores, 97.3% slot packing
//   (1728 jobs = 2.92 x 592 slots; same ratio as R10's 864/296).
//   F_TILE=56 (mult of 8 -> 224B row chunks = 7 full sectors).
//   smem 41.9KB x 4 = 167.7KB/SM; 2048 thr x 32 regs = 64K regs (fits).

#define B        32
#define T        480000
#define WINLEN   400
#define WINSTEP  160
#define NFRAMES  2998
#define F_TILE   56
#define NTILES   54                                    // 54*56 = 3024 >= 2998
#define NPAIRS_T (F_TILE / 2)                          // 28 frame pairs
#define SPAN     ((F_TILE - 1) * WINSTEP + WINLEN + 6 * WINSTEP)  // 10160
#define SM_SZ    (SPAN + SPAN / 32 + 4)                // 10481 floats (~41.9 KB)
#define THREADS  512

__global__ __launch_bounds__(THREADS, 4)
void wav2frames_kernel(const float* __restrict__ x, float* __restrict__ out) {
    extern __shared__ float sm[];

    const int tile = blockIdx.x;
    const int b    = blockIdx.y;
    const int tid  = threadIdx.x;
    const int lane = tid & 31;
    const int w    = tid >> 5;                         // 16 warps

    const int f0 = tile * F_TILE;                      // even
    const int x0 = f0 * WINSTEP;

    // ---- vectorized coalesced fill: gmem float4 -> skewed smem ----
    const float* __restrict__ xb = x + (size_t)b * T + x0;
    const int span  = (x0 + SPAN <= T) ? SPAN : (T - x0);   // multiple of 4
    const int span4 = span >> 2;                       // 2540 at full span
    const float4* __restrict__ xb4 = reinterpret_cast<const float4*>(xb);

    for (int i4 = tid; i4 < span4; i4 += THREADS) {    // ~5 iterations
        const float4 v = xb4[i4];
        const int i = i4 << 2;
        const int p = i + (i >> 5);                    // skew: j + (j>>5)
        sm[p + 0] = v.x;
        sm[p + 1] = v.y;
        sm[p + 2] = v.z;
        sm[p + 3] = v.w;
    }
    __syncthreads();

    float* __restrict__ outb = out + (size_t)b * WINLEN * NFRAMES;

    // ---- main store: 28 frame pairs (lanes) x 16 c-groups (warps) ----
    const int fbase = f0 + 2 * lane;                   // even
    const int jbase = 2 * lane * WINSTEP;              // 320 * lane

    if (lane < NPAIRS_T) {
        #pragma unroll 5
        for (int c = w; c < WINLEN; c += 16) {         // 25 iterations
            const int s = (2 * c) & 7;                 // 0,2,4,6 (even)
            const int f = fbase + s;
            if (f <= NFRAMES - 2) {
                const int j0 = jbase + s * WINSTEP + c;
                const int j1 = j0 + WINSTEP;
                float2 v;
                v.x = sm[j0 + (j0 >> 5)];
                v.y = sm[j1 + (j1 >> 5)];
                *reinterpret_cast<float2*>(outb + (size_t)c * NFRAMES + f) = v;
            }
        }
    }

    // ---- head: tile 0 writes frames [0, s(c)) for each row c ----
    if (tile == 0) {
        for (int idx = tid; idx < WINLEN * 3; idx += THREADS) {
            const int c = idx / 3;
            const int m = idx - 3 * c;                 // pair slot 0..2
            const int s = (2 * c) & 7;
            if (2 * m < s) {
                const int fh = 2 * m;
                const int j0 = fh * WINSTEP + c;
                const int j1 = j0 + WINSTEP;
                float2 v;
                v.x = sm[j0 + (j0 >> 5)];
                v.y = sm[j1 + (j1 >> 5)];
                *reinterpret_cast<float2*>(outb + (size_t)c * NFRAMES + fh) = v;
            }
        }
    }
}

extern "C" void kernel_launch(void* const* d_in, const int* in_sizes, int n_in,
                              void* d_out, int out_size) {
    const float* x = (const float*)d_in[0];            // (32, 1, 480000) fp32
    // d_in[1] = W (identity, unused), d_in[2] = winstep (fixed 160, unused)
    float* out = (float*)d_out;                        // (32, 400, 2998) fp32

    static bool configured = false;
    if (!configured) {
        cudaFuncSetAttribute(wav2frames_kernel,
                             cudaFuncAttributeMaxDynamicSharedMemorySize,
                             SM_SZ * (int)sizeof(float));
        configured = true;
    }

    dim3 grid(NTILES, B);                              // 54 x 32 = 1728 CTAs
    wav2frames_kernel<<<grid, THREADS, SM_SZ * sizeof(float)>>>(x, out);
}

// round 16
// speedup vs baseline: 1.2600x; 1.2600x over previous
#include <cuda_runtime.h>
#include <cuda_bf16.h>

// Wav2Frames: out[b, c, f] = x[b, f*WINSTEP + c]
// x: (32, 1, 480000) fp32 -> out: (32, 400, 2998) fp32
//
// FINAL = R10/R14 (twice-reproduced session best: 34.0-34.4us kernel,
// 39.3-39.4us bench, rel_err 0).
//
// Load-bearing mechanisms (each confirmed by A/B on GB300):
//  1. Per-row sector shift s(c)=(2c)&7: solves 24c + 4s == 0 (mod 32), so
//     every per-row 448B store chunk is sector-aligned -> no partial-sector
//     DRAM read-modify-write on the 153MB write stream (R6: -2.3us).
//  2. F_TILE=112 -> 864 jobs ~ 97.3% of the 296 concurrent CTA slots
//     (2 CTAs/SM x 148 SMs, 3 rounds) -> minimal tail idle (R10: -1.3us).
//  3. smem staging with skew j+(j>>5): conflict-free float4->STS fill,
//     2-way LDS drain (measured faster than the conflict-free LDS.64
//     variant, R3); coalesced float2 frame-pair stores.
//  Falsified: pipelining (R4), streaming hints (R12: L2 residency of the
//  write stream is load-bearing), 128B alignment (R9: read amplification),
//  finer CTAs (R15), perfect packing (R11), predicate hoisting (R13).

#define B        32
#define T        480000
#define WINLEN   400
#define WINSTEP  160
#define NFRAMES  2998
#define F_TILE   112
#define NTILES   27                                    // 27*112 = 3024 >= 2998
#define NPAIRS_T (F_TILE / 2)                          // 56 frame pairs
#define SPAN     ((F_TILE - 1) * WINSTEP + WINLEN + 6 * WINSTEP)  // 19120
#define SM_SZ    (SPAN + SPAN / 32 + 4)                // 19721 floats (~78.9 KB)
#define THREADS  1024

__global__ __launch_bounds__(THREADS, 2)
void wav2frames_kernel(const float* __restrict__ x, float* __restrict__ out) {
    extern __shared__ float sm[];

    const int tile = blockIdx.x;
    const int b    = blockIdx.y;
    const int tid  = threadIdx.x;
    const int lane = tid & 31;
    const int w    = tid >> 5;                         // 32 warps

    const int f0 = tile * F_TILE;                      // even
    const int x0 = f0 * WINSTEP;

    // ---- vectorized coalesced fill: gmem float4 -> skewed smem ----
    const float* __restrict__ xb = x + (size_t)b * T + x0;
    const int span  = (x0 + SPAN <= T) ? SPAN : (T - x0);   // multiple of 4
    const int span4 = span >> 2;
    const float4* __restrict__ xb4 = reinterpret_cast<const float4*>(xb);

    for (int i4 = tid; i4 < span4; i4 += THREADS) {    // ~5 iterations
        const float4 v = xb4[i4];
        const int i = i4 << 2;
        const int p = i + (i >> 5);                    // skew: j + (j>>5)
        sm[p + 0] = v.x;
        sm[p + 1] = v.y;
        sm[p + 2] = v.z;
        sm[p + 3] = v.w;
    }
    __syncthreads();

    float* __restrict__ outb = out + (size_t)b * WINLEN * NFRAMES;

    // ---- main store: 56 frame pairs x 16 c-groups, sector-aligned chunks ----
    const int q      = w & 1;
    const int cg     = w >> 1;                         // 0..15
    const int fp_idx = lane + 32 * q;                  // 0..63 (>=56 idle)
    const int fbase  = f0 + 2 * fp_idx;                // even
    const int jbase  = 2 * fp_idx * WINSTEP;           // 320 * fp_idx

    if (fp_idx < NPAIRS_T) {
        #pragma unroll 5
        for (int c = cg; c < WINLEN; c += 16) {        // 25 iterations
            const int s = (2 * c) & 7;                 // 0,2,4,6 (even)
            const int f = fbase + s;
            if (f <= NFRAMES - 2) {
                const int j0 = jbase + s * WINSTEP + c;
                const int j1 = j0 + WINSTEP;
                float2 v;
                v.x = sm[j0 + (j0 >> 5)];
                v.y = sm[j1 + (j1 >> 5)];
                *reinterpret_cast<float2*>(outb + (size_t)c * NFRAMES + f) = v;
            }
        }
    }

    // ---- head: tile 0 writes frames [0, s(c)) for each row c ----
    if (tile == 0) {
        for (int idx = tid; idx < WINLEN * 3; idx += THREADS) {
            const int c = idx / 3;
            const int m = idx - 3 * c;                 // pair slot 0..2
            const int s = (2 * c) & 7;
            if (2 * m < s) {
                const int fh = 2 * m;
                const int j0 = fh * WINSTEP + c;
                const int j1 = j0 + WINSTEP;
                float2 v;
                v.x = sm[j0 + (j0 >> 5)];
                v.y = sm[j1 + (j1 >> 5)];
                *reinterpret_cast<float2*>(outb + (size_t)c * NFRAMES + fh) = v;
            }
        }
    }
}

extern "C" void kernel_launch(void* const* d_in, const int* in_sizes, int n_in,
                              void* d_out, int out_size) {
    const float* x = (const float*)d_in[0];            // (32, 1, 480000) fp32
    // d_in[1] = W (identity, unused), d_in[2] = winstep (fixed 160, unused)
    float* out = (float*)d_out;                        // (32, 400, 2998) fp32

    static bool configured = false;
    if (!configured) {
        cudaFuncSetAttribute(wav2frames_kernel,
                             cudaFuncAttributeMaxDynamicSharedMemorySize,
                             SM_SZ * (int)sizeof(float));
        configured = true;
    }

    dim3 grid(NTILES, B);                              // 27 x 32 = 864 CTAs
    wav2frames_kernel<<<grid, THREADS, SM_SZ * sizeof(float)>>>(x, out);
}